// round 9
// baseline (speedup 1.0000x reference)
#include <cuda_runtime.h>

#define BB 16
#define CC 1024
#define NLOC 3136            // 16*14*14
#define N4 784               // NLOC/4
#define CSPLIT 8
#define CCHUNK 128           // CC/CSPLIT
#define NBLK_X 7
#define BLOCKS_PER_B (NBLK_X * CSPLIT)   // 56
#define NITER 7              // ceil(N4/128)
#define MARGIN 0.2f
#define INV_TEMP 1000.0f
#define SCALE 100000.0f

// Zero at module load; tail blocks re-zero after consuming -> every replay
// starts clean (deterministic).
__device__ float4 g_pd[BB * N4];
__device__ float4 g_nd[BB * N4];
__device__ float  g_loss[BB];
__device__ unsigned int g_cnt[BB];
__device__ unsigned int g_cnt2;

__global__ void __launch_bounds__(128)
fused_kernel(const float* __restrict__ ft,
             const float* __restrict__ pos,
             const float* __restrict__ neg,
             float* __restrict__ out, int out_size)
{
    __shared__ float  s_pos[CCHUNK];
    __shared__ float  s_neg[CCHUNK];
    __shared__ float4 s_pd[N4];      // 12.5 KB (epilogue only)
    __shared__ float4 s_nd[N4];      // 12.5 KB (epilogue only)
    __shared__ float  red[4];
    __shared__ float  red2[4];
    __shared__ int    s_last;

    const int tid = threadIdx.x;
    const int b   = blockIdx.z;
    const int cs  = blockIdx.y;
    const int c0  = cs * CCHUNK;

    s_pos[tid] = pos[b * CC + c0 + tid];
    s_neg[tid] = neg[b * CC + c0 + tid];
    __syncthreads();

    // ---------------- dot phase ----------------
    const int n4 = blockIdx.x * 128 + tid;
    if (n4 < N4) {
        const float4* base = (const float4*)(ft + (size_t)b * CC * NLOC
                                                + (size_t)c0 * NLOC) + n4;
        float4 pd = {0.f, 0.f, 0.f, 0.f};
        float4 nd = {0.f, 0.f, 0.f, 0.f};
#pragma unroll 8
        for (int c = 0; c < CCHUNK; ++c) {
            float4 v = __ldg(base + (size_t)c * N4);
            float sp = s_pos[c], sn = s_neg[c];
            pd.x = fmaf(v.x, sp, pd.x);  pd.y = fmaf(v.y, sp, pd.y);
            pd.z = fmaf(v.z, sp, pd.z);  pd.w = fmaf(v.w, sp, pd.w);
            nd.x = fmaf(v.x, sn, nd.x);  nd.y = fmaf(v.y, sn, nd.y);
            nd.z = fmaf(v.z, sn, nd.z);  nd.w = fmaf(v.w, sn, nd.w);
        }
        float* dp = (float*)&g_pd[b * N4 + n4];
        float* dn = (float*)&g_nd[b * N4 + n4];
        atomicAdd(dp + 0, pd.x);  atomicAdd(dp + 1, pd.y);
        atomicAdd(dp + 2, pd.z);  atomicAdd(dp + 3, pd.w);
        atomicAdd(dn + 0, nd.x);  atomicAdd(dn + 1, nd.y);
        atomicAdd(dn + 2, nd.z);  atomicAdd(dn + 3, nd.w);
    }

    __threadfence();
    __syncthreads();
    if (tid == 0) {
        unsigned int old = atomicAdd(&g_cnt[b], 1u);
        s_last = (old == BLOCKS_PER_B - 1);
        if (s_last) g_cnt[b] = 0;   // self-reset for next replay
    }
    __syncthreads();
    if (!s_last) return;
    __threadfence();                // acquire: see all batch-b REDG results

    // ---------------- epilogue (one block per batch) ----------------
    const float4 z4 = {0.f, 0.f, 0.f, 0.f};

    // pass 1: stage rows to smem, zero globals, block max
    float m = -1e30f;
#pragma unroll
    for (int i = 0; i < NITER; ++i) {
        int idx = tid + i * 128;
        if (idx < N4) {
            float4 pd = g_pd[b * N4 + idx];
            float4 nd = g_nd[b * N4 + idx];
            g_pd[b * N4 + idx] = z4;
            g_nd[b * N4 + idx] = z4;
            s_pd[idx] = pd;
            s_nd[idx] = nd;
            m = fmaxf(m, fmaxf(fmaxf(pd.x, pd.y), fmaxf(pd.z, pd.w)));
        }
    }
#pragma unroll
    for (int o = 16; o > 0; o >>= 1)
        m = fmaxf(m, __shfl_xor_sync(0xffffffffu, m, o));
    if ((tid & 31) == 0) red[tid >> 5] = m;
    __syncthreads();
    const float mx = fmaxf(fmaxf(red[0], red[1]), fmaxf(red[2], red[3]));
    __syncthreads();

    // pass 2: e = exp(...), accumulate Z and sum(lm*e); stash e in s_pd
    float s = 0.0f, le = 0.0f;
#pragma unroll
    for (int i = 0; i < NITER; ++i) {
        int idx = tid + i * 128;
        if (idx < N4) {
            float4 pd = s_pd[idx];
            float4 nd = s_nd[idx];
            float4 e;
            e.x = expf((pd.x - mx) * INV_TEMP);
            e.y = expf((pd.y - mx) * INV_TEMP);
            e.z = expf((pd.z - mx) * INV_TEMP);
            e.w = expf((pd.w - mx) * INV_TEMP);
            s += e.x + e.y + e.z + e.w;
            le = fmaf(fmaxf(MARGIN + (nd.x - pd.x) * SCALE, 0.0f), e.x, le);
            le = fmaf(fmaxf(MARGIN + (nd.y - pd.y) * SCALE, 0.0f), e.y, le);
            le = fmaf(fmaxf(MARGIN + (nd.z - pd.z) * SCALE, 0.0f), e.z, le);
            le = fmaf(fmaxf(MARGIN + (nd.w - pd.w) * SCALE, 0.0f), e.w, le);
            s_pd[idx] = e;
        }
    }
#pragma unroll
    for (int o = 16; o > 0; o >>= 1) {
        s  += __shfl_xor_sync(0xffffffffu, s, o);
        le += __shfl_xor_sync(0xffffffffu, le, o);
    }
    if ((tid & 31) == 0) { red[tid >> 5] = s;  red2[tid >> 5] = le; }
    __syncthreads();
    const float invZ  = 1.0f / (red[0] + red[1] + red[2] + red[3]);
    const float lossb = (red2[0] + red2[1] + red2[2] + red2[3]) * invZ;

    // pass 3: attn = e * invZ
#pragma unroll
    for (int i = 0; i < NITER; ++i) {
        int idx = tid + i * 128;
        if (idx < N4) {
            float4 e = s_pd[idx];
            float4 a;
            a.x = e.x * invZ;  a.y = e.y * invZ;
            a.z = e.z * invZ;  a.w = e.w * invZ;
            ((float4*)(out + b * NLOC))[idx] = a;
        }
    }

    // super-tail: last batch sums the 16 losses, writes scalar
    if (tid == 0) {
        g_loss[b] = lossb;
        __threadfence();
        unsigned int old = atomicAdd(&g_cnt2, 1u);
        if (old == BB - 1) {
            g_cnt2 = 0;   // self-reset
            __threadfence();
            float tot = 0.0f;
#pragma unroll
            for (int bb = 0; bb < BB; ++bb) tot += g_loss[bb];
            if (out_size > BB * NLOC)
                out[BB * NLOC] = tot * (1.0f / (float)BB);
        }
    }
}

extern "C" void kernel_launch(void* const* d_in, const int* in_sizes, int n_in,
                              void* d_out, int out_size)
{
    const float* ft  = (const float*)d_in[0];
    const float* pos = (const float*)d_in[1];
    const float* neg = (const float*)d_in[2];
    float* out = (float*)d_out;

    dim3 grid(NBLK_X, CSPLIT, BB);
    fused_kernel<<<grid, 128>>>(ft, pos, neg, out, out_size);
}